// round 4
// baseline (speedup 1.0000x reference)
#include <cuda_runtime.h>

// MeanAggregator: out[b] = mean over DISTINCT sampled neighbors of features[nbrs[b,s]]
// features: float32 [N=200000, D=256]   (d_in[0])
// nbrs:     int32   [B=32768, S=10]     (d_in[1])
// out:      float32 [B, D]              (d_out)
//
// 1 warp per row; each lane owns float4 segments lane and lane+32 (row is
// 64 float4s). 20 independent gathers per thread -> 10KB in flight per warp.

#define D 256
#define S 10
#define ROWS_PER_CTA 8

__global__ __launch_bounds__(32 * ROWS_PER_CTA)
void mean_agg_kernel(const float* __restrict__ feat,
                     const int* __restrict__ nbrs,
                     float* __restrict__ out,
                     int B)
{
    const int row = blockIdx.x * ROWS_PER_CTA + threadIdx.y;
    if (row >= B) return;
    const int lane = threadIdx.x;            // 0..31

    // Vectorized index load: 40 bytes per row, 8-byte aligned -> 5x int2.
    const int2* __restrict__ nb2 =
        reinterpret_cast<const int2*>(nbrs + (long long)row * S);
    int idx[S];
#pragma unroll
    for (int i = 0; i < 5; ++i) {
        int2 p = nb2[i];
        idx[2 * i]     = p.x;
        idx[2 * i + 1] = p.y;
    }

    // First-occurrence weights (dedup) + distinct count. O(S^2)=45 compares.
    float w[S];
    float n = 0.f;
#pragma unroll
    for (int i = 0; i < S; ++i) {
        bool dup = false;
#pragma unroll
        for (int j = 0; j < i; ++j) dup |= (idx[j] == idx[i]);
        w[i] = dup ? 0.f : 1.f;
        n += w[i];
    }

    // 20 independent weighted gathers (2 float4 segments per lane).
    // __ldcg: L2-only, no useless L1 allocation (no intra-L1 reuse).
    float4 acc0 = make_float4(0.f, 0.f, 0.f, 0.f);
    float4 acc1 = make_float4(0.f, 0.f, 0.f, 0.f);
#pragma unroll
    for (int i = 0; i < S; ++i) {
        const float4* base = reinterpret_cast<const float4*>(
            feat + (long long)idx[i] * D);
        const float4 v0 = __ldcg(base + lane);
        const float4 v1 = __ldcg(base + lane + 32);
        acc0.x += w[i] * v0.x;  acc0.y += w[i] * v0.y;
        acc0.z += w[i] * v0.z;  acc0.w += w[i] * v0.w;
        acc1.x += w[i] * v1.x;  acc1.y += w[i] * v1.y;
        acc1.z += w[i] * v1.z;  acc1.w += w[i] * v1.w;
    }

    const float inv = 1.f / n;
    float4 o0, o1;
    o0.x = acc0.x * inv;  o0.y = acc0.y * inv;
    o0.z = acc0.z * inv;  o0.w = acc0.w * inv;
    o1.x = acc1.x * inv;  o1.y = acc1.y * inv;
    o1.z = acc1.z * inv;  o1.w = acc1.w * inv;

    float4* obase = reinterpret_cast<float4*>(out + (long long)row * D);
    __stcs(obase + lane,      o0);
    __stcs(obase + lane + 32, o1);
}

extern "C" void kernel_launch(void* const* d_in, const int* in_sizes, int n_in,
                              void* d_out, int out_size)
{
    const float* feat = (const float*)d_in[0];
    const int*   nbrs = (const int*)d_in[1];
    float*       out  = (float*)d_out;

    const int B = in_sizes[1] / S;           // 32768

    dim3 block(32, ROWS_PER_CTA);
    dim3 grid((B + ROWS_PER_CTA - 1) / ROWS_PER_CTA);
    mean_agg_kernel<<<grid, block>>>(feat, nbrs, out, B);
}

// round 5
// speedup vs baseline: 1.0171x; 1.0171x over previous
#include <cuda_runtime.h>

// MeanAggregator: out[b] = mean over DISTINCT sampled neighbors of features[nbrs[b,s]]
// features: float32 [N=200000, D=256]   (d_in[0])
// nbrs:     int32   [B=32768, S=10]     (d_in[1])
// out:      float32 [B, D]              (d_out)
//
// 64 lanes per row (float4 each), 4 rows/CTA. Dup weights kept as a 10-bit
// mask (not a float array) and regs capped at 32 to hit full occupancy:
// the kernel is DRAM-throughput-bound, so maximize concurrent warp streams.

#define D 256
#define S 10
#define LANES 64
#define ROWS_PER_CTA 4

__global__ __launch_bounds__(LANES * ROWS_PER_CTA, 8)
void mean_agg_kernel(const float* __restrict__ feat,
                     const int* __restrict__ nbrs,
                     float* __restrict__ out,
                     int B)
{
    const int row = blockIdx.x * ROWS_PER_CTA + threadIdx.y;   // grid exact
    const int lane = threadIdx.x;            // 0..63, owns floats [lane*4, lane*4+4)

    // Vectorized index load: 40 bytes per row, 8-byte aligned -> 5x int2.
    const int2* __restrict__ nb2 =
        reinterpret_cast<const int2*>(nbrs + (long long)row * S);
    int idx[S];
#pragma unroll
    for (int i = 0; i < 5; ++i) {
        int2 p = nb2[i];
        idx[2 * i]     = p.x;
        idx[2 * i + 1] = p.y;
    }

    // Dup mask: bit i set if idx[i] repeats an earlier index. 45 compares.
    unsigned mask = 0;
    float n = 0.f;
#pragma unroll
    for (int i = 0; i < S; ++i) {
        bool dup = false;
#pragma unroll
        for (int j = 0; j < i; ++j) dup |= (idx[j] == idx[i]);
        mask |= dup ? (1u << i) : 0u;
        n += dup ? 0.f : 1.f;
    }

    // Unconditional weighted gathers; __ldcg keeps them out of L1 (no reuse
    // below L2). Weight reconstructed from the mask bit (1 SEL per i).
    float4 acc = make_float4(0.f, 0.f, 0.f, 0.f);
#pragma unroll
    for (int i = 0; i < S; ++i) {
        const float4 v = __ldcg(reinterpret_cast<const float4*>(
            feat + (long long)idx[i] * D + lane * 4));
        const float wi = (mask & (1u << i)) ? 0.f : 1.f;
        acc.x = fmaf(wi, v.x, acc.x);
        acc.y = fmaf(wi, v.y, acc.y);
        acc.z = fmaf(wi, v.z, acc.z);
        acc.w = fmaf(wi, v.w, acc.w);
    }

    const float inv = 1.f / n;
    float4 o;
    o.x = acc.x * inv;
    o.y = acc.y * inv;
    o.z = acc.z * inv;
    o.w = acc.w * inv;

    // Streaming store: output never re-read; keep L2 for feature rows.
    __stcs(reinterpret_cast<float4*>(out + (long long)row * D + lane * 4), o);
}

extern "C" void kernel_launch(void* const* d_in, const int* in_sizes, int n_in,
                              void* d_out, int out_size)
{
    const float* feat = (const float*)d_in[0];
    const int*   nbrs = (const int*)d_in[1];
    float*       out  = (float*)d_out;

    const int B = in_sizes[1] / S;           // 32768

    dim3 block(LANES, ROWS_PER_CTA);
    dim3 grid(B / ROWS_PER_CTA);
    mean_agg_kernel<<<grid, block>>>(feat, nbrs, out, B);
}